// round 13
// baseline (speedup 1.0000x reference)
#include <cuda_runtime.h>
#include <cuda_fp16.h>
#include <cstdint>

// ---------------- problem-size bounds ----------------
#define MAXN 100000
#define MAXE 1600000
#define MAXG 64
#define MAXB ((MAXN + 1023) / 1024)

// ---------------- scratch (device globals: allocation-free) ----------------
__device__ __half g_xh[(size_t)MAXN * 128];     // x in fp16
__device__ __half g_f16a[(size_t)MAXN * 128];   // fp16 ping
__device__ __half g_f16b[(size_t)MAXN * 128];   // fp16 pong
__device__ __half g_f16c[(size_t)MAXN * 256];   // wide fp16 (G3 out)
__device__ __half g_wt[114688];                  // fp16 transposed weights [N][K]
__device__ float  g_f32a[(size_t)MAXN * 128];   // residual (x@Wl+bl)
__device__ float  g_f32b[(size_t)MAXN * 128];   // A4 out (pool input)
__device__ float  g_dis[MAXN];
__device__ int    g_hist[MAXN];
__device__ int    g_off[MAXN + 1];
__device__ int    g_cursor[MAXN];
__device__ int    g_csr_src[MAXE];
__device__ float  g_cnt[MAXG];
__device__ int    g_bsum[MAXB];
__device__ int    g_boff[MAXB];

#define WT1 0
#define WT2 16384
#define WT3 32768
#define WT4 65536
#define WTL 98304

// ---------------- input conversion ----------------
__global__ void k_cvt_x(const float* __restrict__ x, __half* __restrict__ xh, int total4) {
    int i = blockIdx.x * blockDim.x + threadIdx.x;
    if (i >= total4) return;
    float4 v = ((const float4*)x)[i];
    __half2 a = __floats2half2_rn(v.x, v.y);
    __half2 b = __floats2half2_rn(v.z, v.w);
    uint2 u;
    u.x = *(uint32_t*)&a;
    u.y = *(uint32_t*)&b;
    ((uint2*)xh)[i] = u;
}

__global__ void k_cvt_w(const float* __restrict__ W1, const float* __restrict__ W2,
                        const float* __restrict__ W3, const float* __restrict__ W4,
                        const float* __restrict__ Wl) {
    int i = blockIdx.x * blockDim.x + threadIdx.x;
    if (i >= 114688) return;
    const float* W;
    int K, Nn, local;
    if (i < 16384)       { W = W1; K = 128; Nn = 128; local = i; }
    else if (i < 32768)  { W = W2; K = 128; Nn = 128; local = i - 16384; }
    else if (i < 65536)  { W = W3; K = 128; Nn = 256; local = i - 32768; }
    else if (i < 98304)  { W = W4; K = 256; Nn = 128; local = i - 65536; }
    else                 { W = Wl; K = 128; Nn = 128; local = i - 98304; }
    int n = local / K;
    int k = local % K;
    g_wt[i] = __float2half_rn(W[(size_t)k * Nn + n]);
}

// ---------------- CSR build ----------------
__global__ void k_zero_hist(int n) {
    int i = blockIdx.x * blockDim.x + threadIdx.x;
    if (i < n) g_hist[i] = 0;
}

__global__ void k_hist(const int* __restrict__ ei, int E) {
    int e = blockIdx.x * blockDim.x + threadIdx.x;
    if (e < E) atomicAdd(&g_hist[ei[E + e]], 1);
}

__global__ __launch_bounds__(256) void k_scan1(int n) {
    int b = blockIdx.x, t = threadIdx.x;
    int base = b * 1024;
    int s = 0;
    for (int i = t; i < 1024; i += 256) {
        int idx = base + i;
        if (idx < n) s += g_hist[idx];
    }
    __shared__ int sh[256];
    sh[t] = s;
    __syncthreads();
    for (int o = 128; o > 0; o >>= 1) {
        if (t < o) sh[t] += sh[t + o];
        __syncthreads();
    }
    if (t == 0) g_bsum[b] = sh[0];
}

__global__ __launch_bounds__(1024) void k_scan2(int nb) {
    __shared__ int sh[1024];
    int t = threadIdx.x;
    int v = (t < nb) ? g_bsum[t] : 0;
    sh[t] = v;
    __syncthreads();
    for (int o = 1; o < 1024; o <<= 1) {
        int u = (t >= o) ? sh[t - o] : 0;
        __syncthreads();
        sh[t] += u;
        __syncthreads();
    }
    if (t < nb) g_boff[t] = sh[t] - v;
}

__global__ __launch_bounds__(256) void k_scan3(int n, int E) {
    int b = blockIdx.x, t = threadIdx.x;
    int base = b * 1024 + t * 4;
    int v[4];
    int s = 0;
#pragma unroll
    for (int i = 0; i < 4; i++) {
        int idx = base + i;
        v[i] = (idx < n) ? g_hist[idx] : 0;
        s += v[i];
    }
    __shared__ int sh[256];
    sh[t] = s;
    __syncthreads();
    for (int o = 1; o < 256; o <<= 1) {
        int u = (t >= o) ? sh[t - o] : 0;
        __syncthreads();
        sh[t] += u;
        __syncthreads();
    }
    int excl = sh[t] - s + g_boff[b];
#pragma unroll
    for (int i = 0; i < 4; i++) {
        int idx = base + i;
        if (idx < n) {
            g_off[idx] = excl;
            g_cursor[idx] = excl;
            g_dis[idx] = rsqrtf((float)v[i] + 1.0f);
        }
        excl += v[i];
    }
    if (b == 0 && t == 0) g_off[n] = E;
}

__global__ void k_fill(const int* __restrict__ ei, int E) {
    int e = blockIdx.x * blockDim.x + threadIdx.x;
    if (e < E) {
        int s = ei[e];
        int d = ei[E + e];
        int pos = atomicAdd(&g_cursor[d], 1);
        g_csr_src[pos] = s;
    }
}

// ---------------- typed store helpers ----------------
__device__ __forceinline__ void st2(float* p, float2 v) { *(float2*)p = v; }
__device__ __forceinline__ void st2(__half* p, float2 v) {
    *(__half2*)p = __floats2half2_rn(v.x, v.y);
}
__device__ __forceinline__ void st4(float* p, float4 v) { *(float4*)p = v; }
__device__ __forceinline__ void st4(__half* p, float4 v) {
    __half2 a = __floats2half2_rn(v.x, v.y);
    __half2 b = __floats2half2_rn(v.z, v.w);
    uint2 u;
    u.x = *(uint32_t*)&a;
    u.y = *(uint32_t*)&b;
    *(uint2*)p = u;
}

// ---------------- FP16 tensor-core GEMM (mma.sync + ldmatrix) ----------------
__device__ __forceinline__ void mma_f16(float* d, const uint32_t* a, const uint32_t* b) {
    asm volatile(
        "mma.sync.aligned.m16n8k16.row.col.f32.f16.f16.f32 "
        "{%0,%1,%2,%3}, {%4,%5,%6,%7}, {%8,%9}, {%0,%1,%2,%3};"
        : "+f"(d[0]), "+f"(d[1]), "+f"(d[2]), "+f"(d[3])
        : "r"(a[0]), "r"(a[1]), "r"(a[2]), "r"(a[3]), "r"(b[0]), "r"(b[1]));
}

__device__ __forceinline__ void ldsm4(uint32_t& r0, uint32_t& r1, uint32_t& r2,
                                      uint32_t& r3, uint32_t addr) {
    asm volatile("ldmatrix.sync.aligned.m8n8.x4.shared.b16 {%0,%1,%2,%3}, [%4];"
                 : "=r"(r0), "=r"(r1), "=r"(r2), "=r"(r3) : "r"(addr));
}

__device__ __forceinline__ void cp16h(__half* dst, const __half* src, bool pred) {
    uint32_t d = (uint32_t)__cvta_generic_to_shared(dst);
    int sz = pred ? 16 : 0;
    asm volatile("cp.async.cg.shared.global [%0], [%1], 16, %2;\n"
                 :: "r"(d), "l"(src), "r"(sz));
}
#define CP_COMMIT() asm volatile("cp.async.commit_group;\n" ::)
#define CP_WAIT(N)  asm volatile("cp.async.wait_group %0;\n" :: "n"(N))

// Block tile 128x128, BK=64, 8 warps (4m x 2n), warp tile 32x64.
template <bool RELU, typename T0, typename T1>
__global__ __launch_bounds__(256)
void k_gemm_f16(const __half* __restrict__ A, int lda, int K,
                const __half* __restrict__ W0, const __half* __restrict__ W1p, int ldw,
                const float* __restrict__ b0, const float* __restrict__ b1p,
                T0* __restrict__ C0, int ldc0, T1* __restrict__ C1, int ldc1, int M) {
    extern __shared__ __half smem[];
    __half* As = smem;                  // [2][128*64]
    __half* Bs = smem + 2 * 128 * 64;   // [2][128*64]
    uint32_t sbase = (uint32_t)__cvta_generic_to_shared(smem);

    int tid = threadIdx.x;
    int lane = tid & 31;
    int w = tid >> 5;
    int wm = w & 3;
    int wn = w >> 2;
    int m0 = blockIdx.x * 128;
    const __half* W = (blockIdx.y == 0) ? W0 : W1p;
    const float* bias = (blockIdx.y == 0) ? b0 : b1p;

    float acc[2][8][4];
#pragma unroll
    for (int mi = 0; mi < 2; mi++)
#pragma unroll
        for (int nj = 0; nj < 8; nj++)
#pragma unroll
            for (int q = 0; q < 4; q++) acc[mi][nj][q] = 0.f;

    auto stage = [&](int buf, int kt) {
        __half* Ab = As + buf * 8192;
        __half* Bb = Bs + buf * 8192;
#pragma unroll
        for (int it = 0; it < 4; it++) {
            int idx = it * 256 + tid;
            int r = idx >> 3;
            int ch = idx & 7;
            bool pred = (m0 + r) < M;
            const __half* src = pred ? (A + (size_t)(m0 + r) * lda + kt + ch * 8) : A;
            cp16h(Ab + r * 64 + ((ch ^ (r & 7)) << 3), src, pred);
        }
#pragma unroll
        for (int it = 0; it < 4; it++) {
            int idx = it * 256 + tid;
            int n = idx >> 3;
            int ch = idx & 7;
            const __half* src = W + (size_t)n * ldw + kt + ch * 8;
            cp16h(Bb + n * 64 + ((ch ^ (n & 7)) << 3), src, true);
        }
        CP_COMMIT();
    };

    int g = lane >> 3;
    int lrow = lane & 7;

    int nk = K >> 6;                    // BK = 64
    stage(0, 0);
    for (int t = 0; t < nk; t++) {
        int cur = t & 1;
        if (t + 1 < nk) {
            stage(cur ^ 1, (t + 1) * 64);
            CP_WAIT(1);
        } else {
            CP_WAIT(0);
        }
        __syncthreads();

        uint32_t abase = sbase + (cur * 8192) * 2;
        uint32_t bbase = sbase + (2 * 8192 + cur * 8192) * 2;
#pragma unroll
        for (int kc = 0; kc < 4; kc++) {
            int c0 = kc * 2;
            uint32_t a[2][4];
#pragma unroll
            for (int mi = 0; mi < 2; mi++) {
                int r = wm * 32 + mi * 16 + (g & 1) * 8 + lrow;
                int ch = c0 + (g >> 1);
                uint32_t addr = abase + ((r * 64 + ((ch ^ (r & 7)) << 3)) << 1);
                ldsm4(a[mi][0], a[mi][1], a[mi][2], a[mi][3], addr);
            }
            uint32_t b[8][2];
#pragma unroll
            for (int p = 0; p < 4; p++) {
                int n = wn * 64 + p * 16 + (g >> 1) * 8 + lrow;
                int ch = c0 + (g & 1);
                uint32_t addr = bbase + ((n * 64 + ((ch ^ (n & 7)) << 3)) << 1);
                ldsm4(b[2 * p][0], b[2 * p][1], b[2 * p + 1][0], b[2 * p + 1][1], addr);
            }
#pragma unroll
            for (int mi = 0; mi < 2; mi++)
#pragma unroll
                for (int nj = 0; nj < 8; nj++)
                    mma_f16(acc[mi][nj], a[mi], b[nj]);
        }
        __syncthreads();
    }

#pragma unroll
    for (int mi = 0; mi < 2; mi++) {
        int r = m0 + wm * 32 + mi * 16 + (lane >> 2);
#pragma unroll
        for (int nj = 0; nj < 8; nj++) {
            int cl = wn * 64 + nj * 8 + 2 * (lane & 3);
            float bx = 0.f, by = 0.f;
            if (bias) { bx = bias[cl]; by = bias[cl + 1]; }
            float2 v0 = make_float2(acc[mi][nj][0] + bx, acc[mi][nj][1] + by);
            float2 v1 = make_float2(acc[mi][nj][2] + bx, acc[mi][nj][3] + by);
            if (RELU) {
                v0.x = fmaxf(v0.x, 0.f); v0.y = fmaxf(v0.y, 0.f);
                v1.x = fmaxf(v1.x, 0.f); v1.y = fmaxf(v1.y, 0.f);
            }
            if (blockIdx.y == 0) {
                if (r < M)     st2(C0 + (size_t)r * ldc0 + cl, v0);
                if (r + 8 < M) st2(C0 + (size_t)(r + 8) * ldc0 + cl, v1);
            } else {
                if (r < M)     st2(C1 + (size_t)r * ldc1 + cl, v0);
                if (r + 8 < M) st2(C1 + (size_t)(r + 8) * ldc1 + cl, v1);
            }
        }
    }
}

// ---------------- fused CSR gather, unroll-4 (MLP=4 row loads in flight) ----------------
template <bool RELU, typename OutT>
__global__ __launch_bounds__(256)
void k_aggregate(const __half* __restrict__ h, int ldh,
                 const float* __restrict__ bias,
                 OutT* __restrict__ out, int ldo, int n) {
    int d = (blockIdx.x * blockDim.x + threadIdx.x) >> 5;
    int lane = threadIdx.x & 31;
    if (d >= n) return;
    float disd = g_dis[d];
    int start = g_off[d];
    int end = g_off[d + 1];
    float4 acc;
    {
        float sn = disd * disd;
        uint2 v = *((const uint2*)(h + (size_t)d * ldh) + lane);
        float2 f01 = __half22float2(*(__half2*)&v.x);
        float2 f23 = __half22float2(*(__half2*)&v.y);
        acc = make_float4(f01.x * sn, f01.y * sn, f23.x * sn, f23.y * sn);
    }
    int j = start;
    // main unrolled body: 4 independent row loads in flight
    for (; j + 4 <= end; j += 4) {
        int s0 = g_csr_src[j];
        int s1 = g_csr_src[j + 1];
        int s2 = g_csr_src[j + 2];
        int s3 = g_csr_src[j + 3];
        float n0 = disd * g_dis[s0];
        float n1 = disd * g_dis[s1];
        float n2 = disd * g_dis[s2];
        float n3 = disd * g_dis[s3];
        uint2 v0 = *((const uint2*)(h + (size_t)s0 * ldh) + lane);
        uint2 v1 = *((const uint2*)(h + (size_t)s1 * ldh) + lane);
        uint2 v2 = *((const uint2*)(h + (size_t)s2 * ldh) + lane);
        uint2 v3 = *((const uint2*)(h + (size_t)s3 * ldh) + lane);
        float2 a0 = __half22float2(*(__half2*)&v0.x), b0 = __half22float2(*(__half2*)&v0.y);
        float2 a1 = __half22float2(*(__half2*)&v1.x), b1 = __half22float2(*(__half2*)&v1.y);
        float2 a2 = __half22float2(*(__half2*)&v2.x), b2 = __half22float2(*(__half2*)&v2.y);
        float2 a3 = __half22float2(*(__half2*)&v3.x), b3 = __half22float2(*(__half2*)&v3.y);
        acc.x += a0.x * n0 + a1.x * n1;
        acc.y += a0.y * n0 + a1.y * n1;
        acc.z += b0.x * n0 + b1.x * n1;
        acc.w += b0.y * n0 + b1.y * n1;
        acc.x += a2.x * n2 + a3.x * n3;
        acc.y += a2.y * n2 + a3.y * n3;
        acc.z += b2.x * n2 + b3.x * n3;
        acc.w += b2.y * n2 + b3.y * n3;
    }
    // 2-edge step
    if (j + 2 <= end) {
        int s0 = g_csr_src[j];
        int s1 = g_csr_src[j + 1];
        float n0 = disd * g_dis[s0];
        float n1 = disd * g_dis[s1];
        uint2 v0 = *((const uint2*)(h + (size_t)s0 * ldh) + lane);
        uint2 v1 = *((const uint2*)(h + (size_t)s1 * ldh) + lane);
        float2 a0 = __half22float2(*(__half2*)&v0.x), b0 = __half22float2(*(__half2*)&v0.y);
        float2 a1 = __half22float2(*(__half2*)&v1.x), b1 = __half22float2(*(__half2*)&v1.y);
        acc.x += a0.x * n0 + a1.x * n1;
        acc.y += a0.y * n0 + a1.y * n1;
        acc.z += b0.x * n0 + b1.x * n1;
        acc.w += b0.y * n0 + b1.y * n1;
        j += 2;
    }
    if (j < end) {
        int s0 = g_csr_src[j];
        float n0 = disd * g_dis[s0];
        uint2 v0 = *((const uint2*)(h + (size_t)s0 * ldh) + lane);
        float2 a0 = __half22float2(*(__half2*)&v0.x), b0 = __half22float2(*(__half2*)&v0.y);
        acc.x += a0.x * n0;
        acc.y += a0.y * n0;
        acc.z += b0.x * n0;
        acc.w += b0.y * n0;
    }
    float4 bb = make_float4(0.f, 0.f, 0.f, 0.f);
    if (bias) bb = *(const float4*)(bias + lane * 4);
    float4 r = make_float4(acc.x + bb.x, acc.y + bb.y, acc.z + bb.z, acc.w + bb.w);
    if (RELU) {
        r.x = fmaxf(r.x, 0.f);
        r.y = fmaxf(r.y, 0.f);
        r.z = fmaxf(r.z, 0.f);
        r.w = fmaxf(r.w, 0.f);
    }
    st4(out + (size_t)d * ldo + lane * 4, r);
}

// ---------------- pooling ----------------
__global__ void k_zero_pool(float* __restrict__ out, int total, int G) {
    int i = blockIdx.x * blockDim.x + threadIdx.x;
    if (i < total) out[i] = 0.f;
    if (i < G) g_cnt[i] = 0.f;
}

__global__ __launch_bounds__(128)
void k_pool(const float* __restrict__ P, int ldp,
            const float* __restrict__ Q, int ldq,
            const int* __restrict__ batch, float* __restrict__ out, int n) {
    int f = threadIdx.x;
    int base = blockIdx.x * 256;
    float acc = 0.f;
    float cnt = 0.f;
    int cur = -1;
    for (int k = 0; k < 256; k++) {
        int i = base + k;
        if (i >= n) break;
        int g = batch[i];
        if (g != cur) {
            if (cur >= 0) {
                atomicAdd(&out[cur * 128 + f], acc);
                if (f == 0) atomicAdd(&g_cnt[cur], cnt);
            }
            cur = g;
            acc = 0.f;
            cnt = 0.f;
        }
        acc += P[(size_t)i * ldp + f] + Q[(size_t)i * ldq + f];
        cnt += 1.f;
    }
    if (cur >= 0) {
        atomicAdd(&out[cur * 128 + f], acc);
        if (f == 0) atomicAdd(&g_cnt[cur], cnt);
    }
}

__global__ void k_div(float* __restrict__ out, int total) {
    int i = blockIdx.x * blockDim.x + threadIdx.x;
    if (i < total) {
        int g = i >> 7;
        out[i] /= fmaxf(g_cnt[g], 1.0f);
    }
}

// ---------------- launch ----------------
extern "C" void kernel_launch(void* const* d_in, const int* in_sizes, int n_in,
                              void* d_out, int out_size) {
    const float* x     = (const float*)d_in[0];
    const int*   ei    = (const int*)d_in[1];
    const int*   batch = (const int*)d_in[2];
    const float* W1 = (const float*)d_in[3];
    const float* b1 = (const float*)d_in[4];
    const float* W2 = (const float*)d_in[5];
    const float* b2 = (const float*)d_in[6];
    const float* W3 = (const float*)d_in[7];
    const float* b3 = (const float*)d_in[8];
    const float* W4 = (const float*)d_in[9];
    const float* b4 = (const float*)d_in[10];
    const float* Wl = (const float*)d_in[11];
    const float* bl = (const float*)d_in[12];
    float* out = (float*)d_out;

    const int F = 128;
    int N = in_sizes[0] / F;
    int E = in_sizes[1] / 2;
    int G = out_size / 128;

    __half *xh, *f16a, *f16b, *f16c, *wt;
    float *f32a, *f32b;
    cudaGetSymbolAddress((void**)&xh, g_xh);
    cudaGetSymbolAddress((void**)&f16a, g_f16a);
    cudaGetSymbolAddress((void**)&f16b, g_f16b);
    cudaGetSymbolAddress((void**)&f16c, g_f16c);
    cudaGetSymbolAddress((void**)&wt, g_wt);
    cudaGetSymbolAddress((void**)&f32a, g_f32a);
    cudaGetSymbolAddress((void**)&f32b, g_f32b);

    const int SMEM = 4 * 8192 * (int)sizeof(__half);  // 64 KB
    static bool attr_set = false;
    if (!attr_set) {
        cudaFuncSetAttribute(k_gemm_f16<false, __half, float>,
                             cudaFuncAttributeMaxDynamicSharedMemorySize, SMEM);
        cudaFuncSetAttribute(k_gemm_f16<false, __half, __half>,
                             cudaFuncAttributeMaxDynamicSharedMemorySize, SMEM);
        cudaFuncSetAttribute(k_gemm_f16<true, __half, __half>,
                             cudaFuncAttributeMaxDynamicSharedMemorySize, SMEM);
        attr_set = true;
    }

    int MB = (N + 127) / 128;
    int aggBlocks = (N * 32 + 255) / 256;
    int nb = (N + 1023) / 1024;

    k_cvt_w<<<(114688 + 255) / 256, 256>>>(W1, W2, W3, W4, Wl);          // 0
    k_cvt_x<<<(N * 32 + 255) / 256, 256>>>(x, xh, N * 32);               // 1
    k_zero_hist<<<(N + 255) / 256, 256>>>(N);                             // 2
    // ---- G1: xh@[W1 -> f16a | Wl(+bl) -> f32a] ----                    // 3 (profiled)
    k_gemm_f16<false, __half, float><<<dim3(MB, 2), 256, SMEM>>>(
        xh, 128, 128, wt + WT1, wt + WTL, 128, nullptr, bl, f16a, 128, f32a, 128, N);
    k_hist<<<(E + 255) / 256, 256>>>(ei, E);                              // 4
    k_scan1<<<nb, 256>>>(N);                                              // 5
    k_scan2<<<1, 1024>>>(nb);                                             // 6
    k_scan3<<<nb, 256>>>(N, E);                                           // 7
    k_fill<<<(E + 255) / 256, 256>>>(ei, E);                              // 8

    // ---- A1: agg(f16a) + b1, relu -> f16b ----
    k_aggregate<true, __half><<<aggBlocks, 256>>>(f16a, 128, b1, f16b, 128, N);
    // ---- G2: f16b @ W2 -> f16a ----
    k_gemm_f16<false, __half, __half><<<dim3(MB, 1), 256, SMEM>>>(
        f16b, 128, 128, wt + WT2, nullptr, 128, nullptr, nullptr,
        f16a, 128, (__half*)nullptr, 128, N);
    // ---- A2: agg(f16a) + b2, relu -> f16b ----
    k_aggregate<true, __half><<<aggBlocks, 256>>>(f16a, 128, b2, f16b, 128, N);
    // ---- A3 (reordered): agg(f16b) -> f16a ----
    k_aggregate<false, __half><<<aggBlocks, 256>>>(f16b, 128, nullptr, f16a, 128, N);
    // ---- G3: f16a @ W3 + b3, relu -> f16c (N x 256) ----
    k_gemm_f16<true, __half, __half><<<dim3(MB, 2), 256, SMEM>>>(
        f16a, 128, 128, wt + WT3, wt + WT3 + 128 * 128, 128, b3, b3 + 128,
        f16c, 256, f16c + 128, 256, N);
    // ---- G4: f16c @ W4 -> f16b (K=256) ----
    k_gemm_f16<false, __half, __half><<<dim3(MB, 1), 256, SMEM>>>(
        f16c, 256, 256, wt + WT4, nullptr, 256, nullptr, nullptr,
        f16b, 128, (__half*)nullptr, 128, N);
    // ---- A4: agg(f16b) + b4 -> f32b ----
    k_aggregate<false, float><<<aggBlocks, 256>>>(f16b, 128, b4, f32b, 128, N);

    // ---- global mean pool: f32b (conv out) + f32a (residual) ----
    k_zero_pool<<<(out_size + 255) / 256, 256>>>(out, out_size, G);
    k_pool<<<(N + 255) / 256, 128>>>(f32b, 128, f32a, 128, batch, out, N);
    k_div<<<(out_size + 255) / 256, 256>>>(out, out_size);
}

// round 15
// speedup vs baseline: 1.2301x; 1.2301x over previous
#include <cuda_runtime.h>
#include <cuda_fp16.h>
#include <cstdint>

// ---------------- problem-size bounds ----------------
#define MAXN 100000
#define MAXE 1600000
#define MAXG 64
#define MAXB ((MAXN + 1023) / 1024)

// ---------------- scratch (device globals: allocation-free) ----------------
__device__ __half g_xh[(size_t)MAXN * 128];     // x in fp16
__device__ __half g_f16a[(size_t)MAXN * 128];   // fp16 ping
__device__ __half g_f16b[(size_t)MAXN * 128];   // fp16 pong
__device__ __half g_f16c[(size_t)MAXN * 256];   // wide fp16 (G3 out)
__device__ __half g_f16r[(size_t)MAXN * 128];   // residual (x@Wl+bl) fp16
__device__ __half g_wt[114688];                  // fp16 transposed weights [N][K]
__device__ float  g_dis[MAXN];
__device__ int    g_hist[MAXN];
__device__ int    g_off[MAXN + 1];
__device__ int    g_cursor[MAXN];
__device__ int    g_csr_src[MAXE];
__device__ float  g_cnt[MAXG];
__device__ int    g_bsum[MAXB];
__device__ int    g_boff[MAXB];

#define WT1 0
#define WT2 16384
#define WT3 32768
#define WT4 65536
#define WTL 98304

// ---------------- input conversion ----------------
__global__ void k_cvt_x(const float* __restrict__ x, __half* __restrict__ xh, int total4) {
    int i = blockIdx.x * blockDim.x + threadIdx.x;
    if (i >= total4) return;
    float4 v = ((const float4*)x)[i];
    __half2 a = __floats2half2_rn(v.x, v.y);
    __half2 b = __floats2half2_rn(v.z, v.w);
    uint2 u;
    u.x = *(uint32_t*)&a;
    u.y = *(uint32_t*)&b;
    ((uint2*)xh)[i] = u;
}

__global__ void k_cvt_w(const float* __restrict__ W1, const float* __restrict__ W2,
                        const float* __restrict__ W3, const float* __restrict__ W4,
                        const float* __restrict__ Wl) {
    int i = blockIdx.x * blockDim.x + threadIdx.x;
    if (i >= 114688) return;
    const float* W;
    int K, Nn, local;
    if (i < 16384)       { W = W1; K = 128; Nn = 128; local = i; }
    else if (i < 32768)  { W = W2; K = 128; Nn = 128; local = i - 16384; }
    else if (i < 65536)  { W = W3; K = 128; Nn = 256; local = i - 32768; }
    else if (i < 98304)  { W = W4; K = 256; Nn = 128; local = i - 65536; }
    else                 { W = Wl; K = 128; Nn = 128; local = i - 98304; }
    int n = local / K;
    int k = local % K;
    g_wt[i] = __float2half_rn(W[(size_t)k * Nn + n]);
}

// ---------------- CSR build ----------------
__global__ void k_zero_hist(int n) {
    int i = blockIdx.x * blockDim.x + threadIdx.x;
    if (i < n) g_hist[i] = 0;
}

__global__ void k_hist(const int* __restrict__ ei, int E) {
    int e = blockIdx.x * blockDim.x + threadIdx.x;
    if (e < E) atomicAdd(&g_hist[ei[E + e]], 1);
}

__global__ __launch_bounds__(256) void k_scan1(int n) {
    int b = blockIdx.x, t = threadIdx.x;
    int base = b * 1024;
    int s = 0;
    for (int i = t; i < 1024; i += 256) {
        int idx = base + i;
        if (idx < n) s += g_hist[idx];
    }
    __shared__ int sh[256];
    sh[t] = s;
    __syncthreads();
    for (int o = 128; o > 0; o >>= 1) {
        if (t < o) sh[t] += sh[t + o];
        __syncthreads();
    }
    if (t == 0) g_bsum[b] = sh[0];
}

__global__ __launch_bounds__(1024) void k_scan2(int nb) {
    __shared__ int sh[1024];
    int t = threadIdx.x;
    int v = (t < nb) ? g_bsum[t] : 0;
    sh[t] = v;
    __syncthreads();
    for (int o = 1; o < 1024; o <<= 1) {
        int u = (t >= o) ? sh[t - o] : 0;
        __syncthreads();
        sh[t] += u;
        __syncthreads();
    }
    if (t < nb) g_boff[t] = sh[t] - v;
}

__global__ __launch_bounds__(256) void k_scan3(int n, int E) {
    int b = blockIdx.x, t = threadIdx.x;
    int base = b * 1024 + t * 4;
    int v[4];
    int s = 0;
#pragma unroll
    for (int i = 0; i < 4; i++) {
        int idx = base + i;
        v[i] = (idx < n) ? g_hist[idx] : 0;
        s += v[i];
    }
    __shared__ int sh[256];
    sh[t] = s;
    __syncthreads();
    for (int o = 1; o < 256; o <<= 1) {
        int u = (t >= o) ? sh[t - o] : 0;
        __syncthreads();
        sh[t] += u;
        __syncthreads();
    }
    int excl = sh[t] - s + g_boff[b];
#pragma unroll
    for (int i = 0; i < 4; i++) {
        int idx = base + i;
        if (idx < n) {
            g_off[idx] = excl;
            g_cursor[idx] = excl;
            g_dis[idx] = rsqrtf((float)v[i] + 1.0f);
        }
        excl += v[i];
    }
    if (b == 0 && t == 0) g_off[n] = E;
}

__global__ void k_fill(const int* __restrict__ ei, int E) {
    int e = blockIdx.x * blockDim.x + threadIdx.x;
    if (e < E) {
        int s = ei[e];
        int d = ei[E + e];
        int pos = atomicAdd(&g_cursor[d], 1);
        g_csr_src[pos] = s;
    }
}

// ---------------- typed store helpers ----------------
__device__ __forceinline__ void st2(__half* p, float2 v) {
    *(__half2*)p = __floats2half2_rn(v.x, v.y);
}
__device__ __forceinline__ void st4(__half* p, float4 v) {
    __half2 a = __floats2half2_rn(v.x, v.y);
    __half2 b = __floats2half2_rn(v.z, v.w);
    uint2 u;
    u.x = *(uint32_t*)&a;
    u.y = *(uint32_t*)&b;
    *(uint2*)p = u;
}

// ---------------- FP16 tensor-core GEMM (mma.sync + ldmatrix) ----------------
__device__ __forceinline__ void mma_f16(float* d, const uint32_t* a, const uint32_t* b) {
    asm volatile(
        "mma.sync.aligned.m16n8k16.row.col.f32.f16.f16.f32 "
        "{%0,%1,%2,%3}, {%4,%5,%6,%7}, {%8,%9}, {%0,%1,%2,%3};"
        : "+f"(d[0]), "+f"(d[1]), "+f"(d[2]), "+f"(d[3])
        : "r"(a[0]), "r"(a[1]), "r"(a[2]), "r"(a[3]), "r"(b[0]), "r"(b[1]));
}

__device__ __forceinline__ void ldsm4(uint32_t& r0, uint32_t& r1, uint32_t& r2,
                                      uint32_t& r3, uint32_t addr) {
    asm volatile("ldmatrix.sync.aligned.m8n8.x4.shared.b16 {%0,%1,%2,%3}, [%4];"
                 : "=r"(r0), "=r"(r1), "=r"(r2), "=r"(r3) : "r"(addr));
}

__device__ __forceinline__ void cp16h(__half* dst, const __half* src, bool pred) {
    uint32_t d = (uint32_t)__cvta_generic_to_shared(dst);
    int sz = pred ? 16 : 0;
    asm volatile("cp.async.cg.shared.global [%0], [%1], 16, %2;\n"
                 :: "r"(d), "l"(src), "r"(sz));
}
#define CP_COMMIT() asm volatile("cp.async.commit_group;\n" ::)
#define CP_WAIT(N)  asm volatile("cp.async.wait_group %0;\n" :: "n"(N))

// Block tile 128x128, BK=64, 8 warps (4m x 2n), warp tile 32x64.
// A: fp16 row-major; W: fp16 transposed [N][ldw]. grid.y selects weight set,
// bias, output pointer AND optional per-row output scale (pre-scaled gather rows).
template <bool RELU>
__global__ __launch_bounds__(256)
void k_gemm_f16(const __half* __restrict__ A, int lda, int K,
                const __half* __restrict__ W0, const __half* __restrict__ W1p, int ldw,
                const float* __restrict__ b0, const float* __restrict__ b1p,
                __half* __restrict__ C0, int ldc0, __half* __restrict__ C1, int ldc1,
                const float* __restrict__ rs0, const float* __restrict__ rs1, int M) {
    extern __shared__ __half smem[];
    __half* As = smem;                  // [2][128*64]
    __half* Bs = smem + 2 * 128 * 64;   // [2][128*64]
    uint32_t sbase = (uint32_t)__cvta_generic_to_shared(smem);

    int tid = threadIdx.x;
    int lane = tid & 31;
    int w = tid >> 5;
    int wm = w & 3;
    int wn = w >> 2;
    int m0 = blockIdx.x * 128;
    const __half* W = (blockIdx.y == 0) ? W0 : W1p;
    const float* bias = (blockIdx.y == 0) ? b0 : b1p;
    const float* rowscale = (blockIdx.y == 0) ? rs0 : rs1;
    __half* C = (blockIdx.y == 0) ? C0 : C1;
    int ldc = (blockIdx.y == 0) ? ldc0 : ldc1;

    float acc[2][8][4];
#pragma unroll
    for (int mi = 0; mi < 2; mi++)
#pragma unroll
        for (int nj = 0; nj < 8; nj++)
#pragma unroll
            for (int q = 0; q < 4; q++) acc[mi][nj][q] = 0.f;

    auto stage = [&](int buf, int kt) {
        __half* Ab = As + buf * 8192;
        __half* Bb = Bs + buf * 8192;
#pragma unroll
        for (int it = 0; it < 4; it++) {
            int idx = it * 256 + tid;
            int r = idx >> 3;
            int ch = idx & 7;
            bool pred = (m0 + r) < M;
            const __half* src = pred ? (A + (size_t)(m0 + r) * lda + kt + ch * 8) : A;
            cp16h(Ab + r * 64 + ((ch ^ (r & 7)) << 3), src, pred);
        }
#pragma unroll
        for (int it = 0; it < 4; it++) {
            int idx = it * 256 + tid;
            int n = idx >> 3;
            int ch = idx & 7;
            const __half* src = W + (size_t)n * ldw + kt + ch * 8;
            cp16h(Bb + n * 64 + ((ch ^ (n & 7)) << 3), src, true);
        }
        CP_COMMIT();
    };

    int g = lane >> 3;
    int lrow = lane & 7;

    int nk = K >> 6;                    // BK = 64
    stage(0, 0);
    for (int t = 0; t < nk; t++) {
        int cur = t & 1;
        if (t + 1 < nk) {
            stage(cur ^ 1, (t + 1) * 64);
            CP_WAIT(1);
        } else {
            CP_WAIT(0);
        }
        __syncthreads();

        uint32_t abase = sbase + (cur * 8192) * 2;
        uint32_t bbase = sbase + (2 * 8192 + cur * 8192) * 2;
#pragma unroll
        for (int kc = 0; kc < 4; kc++) {
            int c0 = kc * 2;
            uint32_t a[2][4];
#pragma unroll
            for (int mi = 0; mi < 2; mi++) {
                int r = wm * 32 + mi * 16 + (g & 1) * 8 + lrow;
                int ch = c0 + (g >> 1);
                uint32_t addr = abase + ((r * 64 + ((ch ^ (r & 7)) << 3)) << 1);
                ldsm4(a[mi][0], a[mi][1], a[mi][2], a[mi][3], addr);
            }
            uint32_t b[8][2];
#pragma unroll
            for (int p = 0; p < 4; p++) {
                int n = wn * 64 + p * 16 + (g >> 1) * 8 + lrow;
                int ch = c0 + (g & 1);
                uint32_t addr = bbase + ((n * 64 + ((ch ^ (n & 7)) << 3)) << 1);
                ldsm4(b[2 * p][0], b[2 * p][1], b[2 * p + 1][0], b[2 * p + 1][1], addr);
            }
#pragma unroll
            for (int mi = 0; mi < 2; mi++)
#pragma unroll
                for (int nj = 0; nj < 8; nj++)
                    mma_f16(acc[mi][nj], a[mi], b[nj]);
        }
        __syncthreads();
    }

#pragma unroll
    for (int mi = 0; mi < 2; mi++) {
        int r = m0 + wm * 32 + mi * 16 + (lane >> 2);
        float s0 = 1.f, s1 = 1.f;
        if (rowscale) {
            if (r < M)     s0 = rowscale[r];
            if (r + 8 < M) s1 = rowscale[r + 8];
        }
#pragma unroll
        for (int nj = 0; nj < 8; nj++) {
            int cl = wn * 64 + nj * 8 + 2 * (lane & 3);
            float bx = 0.f, by = 0.f;
            if (bias) { bx = bias[cl]; by = bias[cl + 1]; }
            float2 v0 = make_float2(acc[mi][nj][0] + bx, acc[mi][nj][1] + by);
            float2 v1 = make_float2(acc[mi][nj][2] + bx, acc[mi][nj][3] + by);
            if (RELU) {
                v0.x = fmaxf(v0.x, 0.f); v0.y = fmaxf(v0.y, 0.f);
                v1.x = fmaxf(v1.x, 0.f); v1.y = fmaxf(v1.y, 0.f);
            }
            v0.x *= s0; v0.y *= s0;
            v1.x *= s1; v1.y *= s1;
            if (r < M)     st2(C + (size_t)r * ldc + cl, v0);
            if (r + 8 < M) st2(C + (size_t)(r + 8) * ldc + cl, v1);
        }
    }
}

// ---------------- fused CSR gather over pre-scaled rows ----------------
// rows of h are h_true*dis[row]; out_true = disd * (sum_j h'[src_j] + h'[d]).
// POSTSCALE multiplies the final (post-relu) value by disd again (for buffers
// that are themselves gathered next). res (optional) adds a residual row.
template <bool RELU, bool POSTSCALE>
__global__ __launch_bounds__(64)
void k_aggregate(const __half* __restrict__ h,
                 const float* __restrict__ bias,
                 const __half* __restrict__ res,
                 __half* __restrict__ out, int n) {
    int d = (blockIdx.x * 64 + threadIdx.x) >> 5;
    int lane = threadIdx.x & 31;
    if (d >= n) return;
    float disd = g_dis[d];
    int start = g_off[d];
    int end = g_off[d + 1];
    float4 acc;
    {
        uint2 v = *((const uint2*)(h + (size_t)d * 128) + lane);
        float2 f01 = __half22float2(*(__half2*)&v.x);
        float2 f23 = __half22float2(*(__half2*)&v.y);
        acc = make_float4(f01.x, f01.y, f23.x, f23.y);
    }
    for (int j = start; j < end; j++) {
        int s = g_csr_src[j];
        uint2 v = *((const uint2*)(h + (size_t)s * 128) + lane);
        float2 f01 = __half22float2(*(__half2*)&v.x);
        float2 f23 = __half22float2(*(__half2*)&v.y);
        acc.x += f01.x;
        acc.y += f01.y;
        acc.z += f23.x;
        acc.w += f23.y;
    }
    float4 r = make_float4(acc.x * disd, acc.y * disd, acc.z * disd, acc.w * disd);
    if (bias) {
        float4 bb = *(const float4*)(bias + lane * 4);
        r.x += bb.x; r.y += bb.y; r.z += bb.z; r.w += bb.w;
    }
    if (RELU) {
        r.x = fmaxf(r.x, 0.f);
        r.y = fmaxf(r.y, 0.f);
        r.z = fmaxf(r.z, 0.f);
        r.w = fmaxf(r.w, 0.f);
    }
    if (POSTSCALE) {
        r.x *= disd; r.y *= disd; r.z *= disd; r.w *= disd;
    }
    if (res) {
        uint2 v = *((const uint2*)(res + (size_t)d * 128) + lane);
        float2 f01 = __half22float2(*(__half2*)&v.x);
        float2 f23 = __half22float2(*(__half2*)&v.y);
        r.x += f01.x; r.y += f01.y; r.z += f23.x; r.w += f23.y;
    }
    st4(out + (size_t)d * 128 + lane * 4, r);
}

// ---------------- pooling (single fp16 input) ----------------
__global__ void k_zero_pool(float* __restrict__ out, int total, int G) {
    int i = blockIdx.x * blockDim.x + threadIdx.x;
    if (i < total) out[i] = 0.f;
    if (i < G) g_cnt[i] = 0.f;
}

__global__ __launch_bounds__(128)
void k_pool(const __half* __restrict__ P,
            const int* __restrict__ batch, float* __restrict__ out, int n) {
    int f = threadIdx.x;
    int base = blockIdx.x * 256;
    float acc = 0.f;
    float cnt = 0.f;
    int cur = -1;
    for (int k = 0; k < 256; k++) {
        int i = base + k;
        if (i >= n) break;
        int g = batch[i];
        if (g != cur) {
            if (cur >= 0) {
                atomicAdd(&out[cur * 128 + f], acc);
                if (f == 0) atomicAdd(&g_cnt[cur], cnt);
            }
            cur = g;
            acc = 0.f;
            cnt = 0.f;
        }
        acc += __half2float(P[(size_t)i * 128 + f]);
        cnt += 1.f;
    }
    if (cur >= 0) {
        atomicAdd(&out[cur * 128 + f], acc);
        if (f == 0) atomicAdd(&g_cnt[cur], cnt);
    }
}

__global__ void k_div(float* __restrict__ out, int total) {
    int i = blockIdx.x * blockDim.x + threadIdx.x;
    if (i < total) {
        int g = i >> 7;
        out[i] /= fmaxf(g_cnt[g], 1.0f);
    }
}

// ---------------- launch ----------------
extern "C" void kernel_launch(void* const* d_in, const int* in_sizes, int n_in,
                              void* d_out, int out_size) {
    const float* x     = (const float*)d_in[0];
    const int*   ei    = (const int*)d_in[1];
    const int*   batch = (const int*)d_in[2];
    const float* W1 = (const float*)d_in[3];
    const float* b1 = (const float*)d_in[4];
    const float* W2 = (const float*)d_in[5];
    const float* b2 = (const float*)d_in[6];
    const float* W3 = (const float*)d_in[7];
    const float* b3 = (const float*)d_in[8];
    const float* W4 = (const float*)d_in[9];
    const float* b4 = (const float*)d_in[10];
    const float* Wl = (const float*)d_in[11];
    const float* bl = (const float*)d_in[12];
    float* out = (float*)d_out;

    const int F = 128;
    int N = in_sizes[0] / F;
    int E = in_sizes[1] / 2;
    int G = out_size / 128;

    __half *xh, *f16a, *f16b, *f16c, *f16r, *wt;
    float* dis;
    cudaGetSymbolAddress((void**)&xh, g_xh);
    cudaGetSymbolAddress((void**)&f16a, g_f16a);
    cudaGetSymbolAddress((void**)&f16b, g_f16b);
    cudaGetSymbolAddress((void**)&f16c, g_f16c);
    cudaGetSymbolAddress((void**)&f16r, g_f16r);
    cudaGetSymbolAddress((void**)&wt, g_wt);
    cudaGetSymbolAddress((void**)&dis, g_dis);

    const int SMEM = 4 * 8192 * (int)sizeof(__half);  // 64 KB
    static bool attr_set = false;
    if (!attr_set) {
        cudaFuncSetAttribute(k_gemm_f16<false>,
                             cudaFuncAttributeMaxDynamicSharedMemorySize, SMEM);
        cudaFuncSetAttribute(k_gemm_f16<true>,
                             cudaFuncAttributeMaxDynamicSharedMemorySize, SMEM);
        attr_set = true;
    }

    int MB = (N + 127) / 128;
    int aggBlocks = (N + 1) / 2;        // 64-thread blocks, 2 nodes each
    int nb = (N + 1023) / 1024;

    // NOTE: the CSR/dis chain (hist..scan3) must complete before G1, because
    // G1's epilogue pre-scales rows by g_dis. Order: CSR stats first, G1 after
    // scan3; k_fill can run after G1 (A1 is the first consumer of csr_src).
    k_cvt_w<<<(114688 + 255) / 256, 256>>>(W1, W2, W3, W4, Wl);          // 0
    k_cvt_x<<<(N * 32 + 255) / 256, 256>>>(x, xh, N * 32);               // 1
    k_zero_hist<<<(N + 255) / 256, 256>>>(N);                             // 2
    k_hist<<<(E + 255) / 256, 256>>>(ei, E);                              // 3
    k_scan1<<<nb, 256>>>(N);                                              // 4
    k_scan2<<<1, 1024>>>(nb);                                             // 5
    k_scan3<<<nb, 256>>>(N, E);                                           // 6
    // ---- G1: xh@[W1 -> f16a (xdis) | Wl(+bl) -> f16r] ----
    k_gemm_f16<false><<<dim3(MB, 2), 256, SMEM>>>(
        xh, 128, 128, wt + WT1, wt + WTL, 128, nullptr, bl,
        f16a, 128, f16r, 128, dis, nullptr, N);
    k_fill<<<(E + 255) / 256, 256>>>(ei, E);

    // ---- A1: agg(f16a') + b1, relu -> f16b (true values) ----
    k_aggregate<true, false><<<aggBlocks, 64>>>(f16a, b1, nullptr, f16b, N);
    // ---- G2: f16b @ W2 -> f16a (xdis) ----
    k_gemm_f16<false><<<dim3(MB, 1), 256, SMEM>>>(
        f16b, 128, 128, wt + WT2, nullptr, 128, nullptr, nullptr,
        f16a, 128, nullptr, 128, dis, nullptr, N);
    // ---- A2: agg(f16a') + b2, relu, xdis -> f16b (pre-scaled for A3) ----
    k_aggregate<true, true><<<aggBlocks, 64>>>(f16a, b2, nullptr, f16b, N);
    // ---- A3: agg(f16b') -> f16a (true values, G3 input) ----
    k_aggregate<false, false><<<aggBlocks, 64>>>(f16b, nullptr, nullptr, f16a, N);
    // ---- G3: f16a @ W3 + b3, relu -> f16c (N x 256, true values) ----
    k_gemm_f16<true><<<dim3(MB, 2), 256, SMEM>>>(
        f16a, 128, 128, wt + WT3, wt + WT3 + 128 * 128, 128, b3, b3 + 128,
        f16c, 256, f16c + 128, 256, nullptr, nullptr, N);
    // ---- G4: f16c @ W4 -> f16b (xdis), K=256 ----
    k_gemm_f16<false><<<dim3(MB, 1), 256, SMEM>>>(
        f16c, 256, 256, wt + WT4, nullptr, 256, nullptr, nullptr,
        f16b, 128, nullptr, 128, dis, nullptr, N);
    // ---- A4: agg(f16b') + b4 + residual(f16r) -> f16a ----
    k_aggregate<false, false><<<aggBlocks, 64>>>(f16b, b4, f16r, f16a, N);

    // ---- global mean pool over f16a ----
    k_zero_pool<<<(out_size + 255) / 256, 256>>>(out, out_size, G);
    k_pool<<<(N + 255) / 256, 128>>>(f16a, batch, out, N);
    k_div<<<(out_size + 255) / 256, 256>>>(out, out_size);
}

// round 16
// speedup vs baseline: 1.2516x; 1.0175x over previous
#include <cuda_runtime.h>
#include <cuda_fp16.h>
#include <cstdint>

// ---------------- problem-size bounds ----------------
#define MAXN 100000
#define MAXE 1600000
#define MAXG 64
#define MAXB ((MAXN + 1023) / 1024)

// ---------------- scratch (device globals: allocation-free) ----------------
__device__ __half g_xh[(size_t)MAXN * 128];     // x in fp16
__device__ __half g_f16a[(size_t)MAXN * 128];   // fp16 ping
__device__ __half g_f16b[(size_t)MAXN * 128];   // fp16 pong
__device__ __half g_f16c[(size_t)MAXN * 256];   // wide fp16 (G3 out)
__device__ __half g_f16r[(size_t)MAXN * 128];   // residual (x@Wl+bl) fp16
__device__ __half g_wt[114688];                  // fp16 transposed weights [N][K]
__device__ float  g_dis[MAXN];
__device__ int    g_hist[MAXN];
__device__ int    g_off[MAXN + 1];
__device__ int    g_cursor[MAXN];
__device__ int    g_csr_src[MAXE];
__device__ float  g_cnt[MAXG];
__device__ int    g_bsum[MAXB];
__device__ int    g_boff[MAXB];

#define WT1 0
#define WT2 16384
#define WT3 32768
#define WT4 65536
#define WTL 98304

// ---------------- input conversion ----------------
__global__ void k_cvt_x(const float* __restrict__ x, __half* __restrict__ xh, int total4) {
    int i = blockIdx.x * blockDim.x + threadIdx.x;
    if (i >= total4) return;
    float4 v = ((const float4*)x)[i];
    __half2 a = __floats2half2_rn(v.x, v.y);
    __half2 b = __floats2half2_rn(v.z, v.w);
    uint2 u;
    u.x = *(uint32_t*)&a;
    u.y = *(uint32_t*)&b;
    ((uint2*)xh)[i] = u;
}

__global__ void k_cvt_w(const float* __restrict__ W1, const float* __restrict__ W2,
                        const float* __restrict__ W3, const float* __restrict__ W4,
                        const float* __restrict__ Wl) {
    int i = blockIdx.x * blockDim.x + threadIdx.x;
    if (i >= 114688) return;
    const float* W;
    int K, Nn, local;
    if (i < 16384)       { W = W1; K = 128; Nn = 128; local = i; }
    else if (i < 32768)  { W = W2; K = 128; Nn = 128; local = i - 16384; }
    else if (i < 65536)  { W = W3; K = 128; Nn = 256; local = i - 32768; }
    else if (i < 98304)  { W = W4; K = 256; Nn = 128; local = i - 65536; }
    else                 { W = Wl; K = 128; Nn = 128; local = i - 98304; }
    int n = local / K;
    int k = local % K;
    g_wt[i] = __float2half_rn(W[(size_t)k * Nn + n]);
}

// ---------------- CSR build ----------------
__global__ void k_zero_hist(int n) {
    int i = blockIdx.x * blockDim.x + threadIdx.x;
    if (i < n) g_hist[i] = 0;
}

__global__ void k_hist(const int* __restrict__ ei, int E) {
    int e = blockIdx.x * blockDim.x + threadIdx.x;
    if (e < E) atomicAdd(&g_hist[ei[E + e]], 1);
}

__global__ __launch_bounds__(256) void k_scan1(int n) {
    int b = blockIdx.x, t = threadIdx.x;
    int base = b * 1024;
    int s = 0;
    for (int i = t; i < 1024; i += 256) {
        int idx = base + i;
        if (idx < n) s += g_hist[idx];
    }
    __shared__ int sh[256];
    sh[t] = s;
    __syncthreads();
    for (int o = 128; o > 0; o >>= 1) {
        if (t < o) sh[t] += sh[t + o];
        __syncthreads();
    }
    if (t == 0) g_bsum[b] = sh[0];
}

__global__ __launch_bounds__(1024) void k_scan2(int nb) {
    __shared__ int sh[1024];
    int t = threadIdx.x;
    int v = (t < nb) ? g_bsum[t] : 0;
    sh[t] = v;
    __syncthreads();
    for (int o = 1; o < 1024; o <<= 1) {
        int u = (t >= o) ? sh[t - o] : 0;
        __syncthreads();
        sh[t] += u;
        __syncthreads();
    }
    if (t < nb) g_boff[t] = sh[t] - v;
}

__global__ __launch_bounds__(256) void k_scan3(int n, int E) {
    int b = blockIdx.x, t = threadIdx.x;
    int base = b * 1024 + t * 4;
    int v[4];
    int s = 0;
#pragma unroll
    for (int i = 0; i < 4; i++) {
        int idx = base + i;
        v[i] = (idx < n) ? g_hist[idx] : 0;
        s += v[i];
    }
    __shared__ int sh[256];
    sh[t] = s;
    __syncthreads();
    for (int o = 1; o < 256; o <<= 1) {
        int u = (t >= o) ? sh[t - o] : 0;
        __syncthreads();
        sh[t] += u;
        __syncthreads();
    }
    int excl = sh[t] - s + g_boff[b];
#pragma unroll
    for (int i = 0; i < 4; i++) {
        int idx = base + i;
        if (idx < n) {
            g_off[idx] = excl;
            g_cursor[idx] = excl;
            g_dis[idx] = rsqrtf((float)v[i] + 1.0f);
        }
        excl += v[i];
    }
    if (b == 0 && t == 0) g_off[n] = E;
}

__global__ void k_fill(const int* __restrict__ ei, int E) {
    int e = blockIdx.x * blockDim.x + threadIdx.x;
    if (e < E) {
        int s = ei[e];
        int d = ei[E + e];
        int pos = atomicAdd(&g_cursor[d], 1);
        g_csr_src[pos] = s;
    }
}

// ---------------- typed store helpers ----------------
__device__ __forceinline__ void st2(__half* p, float2 v) {
    *(__half2*)p = __floats2half2_rn(v.x, v.y);
}
__device__ __forceinline__ void st4(__half* p, float4 v) {
    __half2 a = __floats2half2_rn(v.x, v.y);
    __half2 b = __floats2half2_rn(v.z, v.w);
    uint2 u;
    u.x = *(uint32_t*)&a;
    u.y = *(uint32_t*)&b;
    *(uint2*)p = u;
}

// ---------------- FP16 tensor-core GEMM (mma.sync + ldmatrix) ----------------
__device__ __forceinline__ void mma_f16(float* d, const uint32_t* a, const uint32_t* b) {
    asm volatile(
        "mma.sync.aligned.m16n8k16.row.col.f32.f16.f16.f32 "
        "{%0,%1,%2,%3}, {%4,%5,%6,%7}, {%8,%9}, {%0,%1,%2,%3};"
        : "+f"(d[0]), "+f"(d[1]), "+f"(d[2]), "+f"(d[3])
        : "r"(a[0]), "r"(a[1]), "r"(a[2]), "r"(a[3]), "r"(b[0]), "r"(b[1]));
}

__device__ __forceinline__ void ldsm4(uint32_t& r0, uint32_t& r1, uint32_t& r2,
                                      uint32_t& r3, uint32_t addr) {
    asm volatile("ldmatrix.sync.aligned.m8n8.x4.shared.b16 {%0,%1,%2,%3}, [%4];"
                 : "=r"(r0), "=r"(r1), "=r"(r2), "=r"(r3) : "r"(addr));
}

__device__ __forceinline__ void cp16h(__half* dst, const __half* src, bool pred) {
    uint32_t d = (uint32_t)__cvta_generic_to_shared(dst);
    int sz = pred ? 16 : 0;
    asm volatile("cp.async.cg.shared.global [%0], [%1], 16, %2;\n"
                 :: "r"(d), "l"(src), "r"(sz));
}
#define CP_COMMIT() asm volatile("cp.async.commit_group;\n" ::)
#define CP_WAIT(N)  asm volatile("cp.async.wait_group %0;\n" :: "n"(N))

// Block tile 64x128, BK=64, 128 threads = 4 warps (2m x 2n), warp tile 32x64.
// 48 KB smem/CTA + 125 regs/thread -> 4 CTAs/SM (vs 2 before): cross-CTA
// overlap hides the syncthreads-bounded pipeline stalls.
// A: fp16 row-major; W: fp16 transposed [N][ldw]. grid.y selects weight set,
// bias, output pointer AND optional per-row output scale (pre-scaled rows).
template <bool RELU>
__global__ __launch_bounds__(128, 4)
void k_gemm_f16(const __half* __restrict__ A, int lda, int K,
                const __half* __restrict__ W0, const __half* __restrict__ W1p, int ldw,
                const float* __restrict__ b0, const float* __restrict__ b1p,
                __half* __restrict__ C0, int ldc0, __half* __restrict__ C1, int ldc1,
                const float* __restrict__ rs0, const float* __restrict__ rs1, int M) {
    extern __shared__ __half smem[];
    // As: [2][64*64] @ 0, Bs: [2][128*64] @ 8192 (halfs)
    __half* As = smem;
    __half* Bs = smem + 2 * 64 * 64;
    uint32_t sbase = (uint32_t)__cvta_generic_to_shared(smem);

    int tid = threadIdx.x;
    int lane = tid & 31;
    int w = tid >> 5;
    int wm = w & 1;
    int wn = w >> 1;
    int m0 = blockIdx.x * 64;
    const __half* W = (blockIdx.y == 0) ? W0 : W1p;
    const float* bias = (blockIdx.y == 0) ? b0 : b1p;
    const float* rowscale = (blockIdx.y == 0) ? rs0 : rs1;
    __half* C = (blockIdx.y == 0) ? C0 : C1;
    int ldc = (blockIdx.y == 0) ? ldc0 : ldc1;

    float acc[2][8][4];
#pragma unroll
    for (int mi = 0; mi < 2; mi++)
#pragma unroll
        for (int nj = 0; nj < 8; nj++)
#pragma unroll
            for (int q = 0; q < 4; q++) acc[mi][nj][q] = 0.f;

    auto stage = [&](int buf, int kt) {
        __half* Ab = As + buf * 4096;
        __half* Bb = Bs + buf * 8192;
#pragma unroll
        for (int it = 0; it < 4; it++) {        // 64 rows x 8 chunks / 128 thr
            int idx = it * 128 + tid;
            int r = idx >> 3;
            int ch = idx & 7;
            bool pred = (m0 + r) < M;
            const __half* src = pred ? (A + (size_t)(m0 + r) * lda + kt + ch * 8) : A;
            cp16h(Ab + r * 64 + ((ch ^ (r & 7)) << 3), src, pred);
        }
#pragma unroll
        for (int it = 0; it < 8; it++) {        // 128 n-rows x 8 chunks / 128 thr
            int idx = it * 128 + tid;
            int n = idx >> 3;
            int ch = idx & 7;
            const __half* src = W + (size_t)n * ldw + kt + ch * 8;
            cp16h(Bb + n * 64 + ((ch ^ (n & 7)) << 3), src, true);
        }
        CP_COMMIT();
    };

    int g = lane >> 3;
    int lrow = lane & 7;

    int nk = K >> 6;                    // BK = 64
    stage(0, 0);
    for (int t = 0; t < nk; t++) {
        int cur = t & 1;
        if (t + 1 < nk) {
            stage(cur ^ 1, (t + 1) * 64);
            CP_WAIT(1);
        } else {
            CP_WAIT(0);
        }
        __syncthreads();

        uint32_t abase = sbase + (cur * 4096) * 2;
        uint32_t bbase = sbase + (2 * 4096 + cur * 8192) * 2;
#pragma unroll
        for (int kc = 0; kc < 4; kc++) {
            int c0 = kc * 2;
            uint32_t a[2][4];
#pragma unroll
            for (int mi = 0; mi < 2; mi++) {
                int r = wm * 32 + mi * 16 + (g & 1) * 8 + lrow;
                int ch = c0 + (g >> 1);
                uint32_t addr = abase + ((r * 64 + ((ch ^ (r & 7)) << 3)) << 1);
                ldsm4(a[mi][0], a[mi][1], a[mi][2], a[mi][3], addr);
            }
            uint32_t b[8][2];
#pragma unroll
            for (int p = 0; p < 4; p++) {
                int n = wn * 64 + p * 16 + (g >> 1) * 8 + lrow;
                int ch = c0 + (g & 1);
                uint32_t addr = bbase + ((n * 64 + ((ch ^ (n & 7)) << 3)) << 1);
                ldsm4(b[2 * p][0], b[2 * p][1], b[2 * p + 1][0], b[2 * p + 1][1], addr);
            }
#pragma unroll
            for (int mi = 0; mi < 2; mi++)
#pragma unroll
                for (int nj = 0; nj < 8; nj++)
                    mma_f16(acc[mi][nj], a[mi], b[nj]);
        }
        __syncthreads();
    }

#pragma unroll
    for (int mi = 0; mi < 2; mi++) {
        int r = m0 + wm * 32 + mi * 16 + (lane >> 2);
        float s0 = 1.f, s1 = 1.f;
        if (rowscale) {
            if (r < M)     s0 = rowscale[r];
            if (r + 8 < M) s1 = rowscale[r + 8];
        }
#pragma unroll
        for (int nj = 0; nj < 8; nj++) {
            int cl = wn * 64 + nj * 8 + 2 * (lane & 3);
            float bx = 0.f, by = 0.f;
            if (bias) { bx = bias[cl]; by = bias[cl + 1]; }
            float2 v0 = make_float2(acc[mi][nj][0] + bx, acc[mi][nj][1] + by);
            float2 v1 = make_float2(acc[mi][nj][2] + bx, acc[mi][nj][3] + by);
            if (RELU) {
                v0.x = fmaxf(v0.x, 0.f); v0.y = fmaxf(v0.y, 0.f);
                v1.x = fmaxf(v1.x, 0.f); v1.y = fmaxf(v1.y, 0.f);
            }
            v0.x *= s0; v0.y *= s0;
            v1.x *= s1; v1.y *= s1;
            if (r < M)     st2(C + (size_t)r * ldc + cl, v0);
            if (r + 8 < M) st2(C + (size_t)(r + 8) * ldc + cl, v1);
        }
    }
}

// ---------------- fused CSR gather over pre-scaled rows ----------------
template <bool RELU, bool POSTSCALE>
__global__ __launch_bounds__(64)
void k_aggregate(const __half* __restrict__ h,
                 const float* __restrict__ bias,
                 const __half* __restrict__ res,
                 __half* __restrict__ out, int n) {
    int d = (blockIdx.x * 64 + threadIdx.x) >> 5;
    int lane = threadIdx.x & 31;
    if (d >= n) return;
    float disd = g_dis[d];
    int start = g_off[d];
    int end = g_off[d + 1];
    float4 acc;
    {
        uint2 v = *((const uint2*)(h + (size_t)d * 128) + lane);
        float2 f01 = __half22float2(*(__half2*)&v.x);
        float2 f23 = __half22float2(*(__half2*)&v.y);
        acc = make_float4(f01.x, f01.y, f23.x, f23.y);
    }
    for (int j = start; j < end; j++) {
        int s = g_csr_src[j];
        uint2 v = *((const uint2*)(h + (size_t)s * 128) + lane);
        float2 f01 = __half22float2(*(__half2*)&v.x);
        float2 f23 = __half22float2(*(__half2*)&v.y);
        acc.x += f01.x;
        acc.y += f01.y;
        acc.z += f23.x;
        acc.w += f23.y;
    }
    float4 r = make_float4(acc.x * disd, acc.y * disd, acc.z * disd, acc.w * disd);
    if (bias) {
        float4 bb = *(const float4*)(bias + lane * 4);
        r.x += bb.x; r.y += bb.y; r.z += bb.z; r.w += bb.w;
    }
    if (RELU) {
        r.x = fmaxf(r.x, 0.f);
        r.y = fmaxf(r.y, 0.f);
        r.z = fmaxf(r.z, 0.f);
        r.w = fmaxf(r.w, 0.f);
    }
    if (POSTSCALE) {
        r.x *= disd; r.y *= disd; r.z *= disd; r.w *= disd;
    }
    if (res) {
        uint2 v = *((const uint2*)(res + (size_t)d * 128) + lane);
        float2 f01 = __half22float2(*(__half2*)&v.x);
        float2 f23 = __half22float2(*(__half2*)&v.y);
        r.x += f01.x; r.y += f01.y; r.z += f23.x; r.w += f23.y;
    }
    st4(out + (size_t)d * 128 + lane * 4, r);
}

// ---------------- pooling (single fp16 input) ----------------
__global__ void k_zero_pool(float* __restrict__ out, int total, int G) {
    int i = blockIdx.x * blockDim.x + threadIdx.x;
    if (i < total) out[i] = 0.f;
    if (i < G) g_cnt[i] = 0.f;
}

__global__ __launch_bounds__(128)
void k_pool(const __half* __restrict__ P,
            const int* __restrict__ batch, float* __restrict__ out, int n) {
    int f = threadIdx.x;
    int base = blockIdx.x * 256;
    float acc = 0.f;
    float cnt = 0.f;
    int cur = -1;
    for (int k = 0; k < 256; k++) {
        int i = base + k;
        if (i >= n) break;
        int g = batch[i];
        if (g != cur) {
            if (cur >= 0) {
                atomicAdd(&out[cur * 128 + f], acc);
                if (f == 0) atomicAdd(&g_cnt[cur], cnt);
            }
            cur = g;
            acc = 0.f;
            cnt = 0.f;
        }
        acc += __half2float(P[(size_t)i * 128 + f]);
        cnt += 1.f;
    }
    if (cur >= 0) {
        atomicAdd(&out[cur * 128 + f], acc);
        if (f == 0) atomicAdd(&g_cnt[cur], cnt);
    }
}

__global__ void k_div(float* __restrict__ out, int total) {
    int i = blockIdx.x * blockDim.x + threadIdx.x;
    if (i < total) {
        int g = i >> 7;
        out[i] /= fmaxf(g_cnt[g], 1.0f);
    }
}

// ---------------- launch ----------------
extern "C" void kernel_launch(void* const* d_in, const int* in_sizes, int n_in,
                              void* d_out, int out_size) {
    const float* x     = (const float*)d_in[0];
    const int*   ei    = (const int*)d_in[1];
    const int*   batch = (const int*)d_in[2];
    const float* W1 = (const float*)d_in[3];
    const float* b1 = (const float*)d_in[4];
    const float* W2 = (const float*)d_in[5];
    const float* b2 = (const float*)d_in[6];
    const float* W3 = (const float*)d_in[7];
    const float* b3 = (const float*)d_in[8];
    const float* W4 = (const float*)d_in[9];
    const float* b4 = (const float*)d_in[10];
    const float* Wl = (const float*)d_in[11];
    const float* bl = (const float*)d_in[12];
    float* out = (float*)d_out;

    const int F = 128;
    int N = in_sizes[0] / F;
    int E = in_sizes[1] / 2;
    int G = out_size / 128;

    __half *xh, *f16a, *f16b, *f16c, *f16r, *wt;
    float* dis;
    cudaGetSymbolAddress((void**)&xh, g_xh);
    cudaGetSymbolAddress((void**)&f16a, g_f16a);
    cudaGetSymbolAddress((void**)&f16b, g_f16b);
    cudaGetSymbolAddress((void**)&f16c, g_f16c);
    cudaGetSymbolAddress((void**)&f16r, g_f16r);
    cudaGetSymbolAddress((void**)&wt, g_wt);
    cudaGetSymbolAddress((void**)&dis, g_dis);

    const int SMEM = (2 * 64 * 64 + 2 * 128 * 64) * (int)sizeof(__half);  // 48 KB
    static bool attr_set = false;
    if (!attr_set) {
        cudaFuncSetAttribute(k_gemm_f16<false>,
                             cudaFuncAttributeMaxDynamicSharedMemorySize, SMEM);
        cudaFuncSetAttribute(k_gemm_f16<true>,
                             cudaFuncAttributeMaxDynamicSharedMemorySize, SMEM);
        attr_set = true;
    }

    int MB = (N + 63) / 64;             // 64-row tiles
    int aggBlocks = (N + 1) / 2;        // 64-thread blocks, 2 nodes each
    int nb = (N + 1023) / 1024;

    // CSR/dis chain must complete before G1 (epilogue pre-scales rows by dis);
    // k_fill may run after G1 (A1 is the first consumer of csr_src).
    k_cvt_w<<<(114688 + 255) / 256, 256>>>(W1, W2, W3, W4, Wl);
    k_cvt_x<<<(N * 32 + 255) / 256, 256>>>(x, xh, N * 32);
    k_zero_hist<<<(N + 255) / 256, 256>>>(N);
    k_hist<<<(E + 255) / 256, 256>>>(ei, E);
    k_scan1<<<nb, 256>>>(N);
    k_scan2<<<1, 1024>>>(nb);
    k_scan3<<<nb, 256>>>(N, E);
    // ---- G1: xh@[W1 -> f16a (xdis) | Wl(+bl) -> f16r] ----
    k_gemm_f16<false><<<dim3(MB, 2), 128, SMEM>>>(
        xh, 128, 128, wt + WT1, wt + WTL, 128, nullptr, bl,
        f16a, 128, f16r, 128, dis, nullptr, N);
    k_fill<<<(E + 255) / 256, 256>>>(ei, E);

    // ---- A1: agg(f16a') + b1, relu -> f16b (true values) ----
    k_aggregate<true, false><<<aggBlocks, 64>>>(f16a, b1, nullptr, f16b, N);
    // ---- G2: f16b @ W2 -> f16a (xdis) ----
    k_gemm_f16<false><<<dim3(MB, 1), 128, SMEM>>>(
        f16b, 128, 128, wt + WT2, nullptr, 128, nullptr, nullptr,
        f16a, 128, nullptr, 128, dis, nullptr, N);
    // ---- A2: agg(f16a') + b2, relu, xdis -> f16b (pre-scaled for A3) ----
    k_aggregate<true, true><<<aggBlocks, 64>>>(f16a, b2, nullptr, f16b, N);
    // ---- A3: agg(f16b') -> f16a (true values, G3 input) ----
    k_aggregate<false, false><<<aggBlocks, 64>>>(f16b, nullptr, nullptr, f16a, N);
    // ---- G3: f16a @ W3 + b3, relu -> f16c (N x 256, true values) ----
    k_gemm_f16<true><<<dim3(MB, 2), 128, SMEM>>>(
        f16a, 128, 128, wt + WT3, wt + WT3 + 128 * 128, 128, b3, b3 + 128,
        f16c, 256, f16c + 128, 256, nullptr, nullptr, N);
    // ---- G4: f16c @ W4 -> f16b (xdis), K=256 ----
    k_gemm_f16<false><<<dim3(MB, 1), 128, SMEM>>>(
        f16c, 256, 256, wt + WT4, nullptr, 256, nullptr, nullptr,
        f16b, 128, nullptr, 128, dis, nullptr, N);
    // ---- A4: agg(f16b') + b4 + residual(f16r) -> f16a ----
    k_aggregate<false, false><<<aggBlocks, 64>>>(f16b, b4, f16r, f16a, N);

    // ---- global mean pool over f16a ----
    k_zero_pool<<<(out_size + 255) / 256, 256>>>(out, out_size, G);
    k_pool<<<(N + 255) / 256, 128>>>(f16a, batch, out, N);
    k_div<<<(out_size + 255) / 256, 256>>>(out, out_size);
}